// round 2
// baseline (speedup 1.0000x reference)
#include <cuda_runtime.h>
#include <math.h>

// Problem constants
#define BB   64
#define FF   1024
#define HID  2048
#define NHD  4
#define KSZ  4
#define HD   512
#define NB   512
#define EPSF 1e-6f
#define RSQRT_HD 0.044194173824159216f   // 1/sqrt(512)

// Output layout: concat(y, C_new, n_new, m_new, conv_state_new), fp32
#define OFF_Y  0
#define OFF_C  65536
#define OFF_N  67174400
#define OFF_M  67305472
#define OFF_CS 67305728

// Scratch (static device memory; no allocations anywhere)
__device__ float g_up_part[8 * 64 * 4096];   // up-GEMM k-split partials
__device__ float g_y_part[16 * 64 * 1024];   // down-GEMM k-split partials
__device__ float g_q  [BB * HID];
__device__ float g_v  [BB * HID];
__device__ float g_ik [BB * HID];            // i_p * k / sqrt(HD)
__device__ float g_cva[BB * HID];            // silu(conv_x)
__device__ float g_sz [BB * HID];            // silu(z)
__device__ float g_h  [BB * HID];            // pre-down-proj hidden
__device__ float g_fp [BB * NHD];
__device__ float g_den[BB * NHD];            // max(|q^T n_new|, exp(-m_new)) + eps

// ---------------------------------------------------------------------------
// GEMM: Y[64, NCOLS] = A[64, LDIN] @ W[K, NCOLS], k-split into gridDim.y
// partials. Thread owns one column, 64 row-accumulators in registers.
// WHICH=0: A = external pointer (inputs), out -> g_up_part
// WHICH=1: A = g_h (device symbol, resolved in device code), out -> g_y_part
// ---------------------------------------------------------------------------
template<int NCOLS, int KCHUNK, int LDIN, int WHICH>
__global__ __launch_bounds__(128) void k_gemm64(const float* __restrict__ Aext,
                                                const float* __restrict__ W)
{
    __shared__ float s_a[64][KCHUNK];
    const int c  = blockIdx.x * 128 + threadIdx.x;
    const int k0 = blockIdx.y * KCHUNK;

    const float* A = WHICH ? (const float*)g_h : Aext;

    for (int i = threadIdx.x; i < 64 * KCHUNK; i += 128) {
        int r = i / KCHUNK, kk = i % KCHUNK;
        s_a[r][kk] = A[r * LDIN + k0 + kk];
    }
    __syncthreads();

    float acc[64];
#pragma unroll
    for (int r = 0; r < 64; r++) acc[r] = 0.f;

#pragma unroll 1
    for (int kk = 0; kk < KCHUNK; kk += 8) {
        float w[8];
#pragma unroll
        for (int j = 0; j < 8; j++)
            w[j] = W[(size_t)(k0 + kk + j) * NCOLS + c];
#pragma unroll
        for (int r = 0; r < 64; r++) {
            float4 a0 = *reinterpret_cast<const float4*>(&s_a[r][kk]);
            float4 a1 = *reinterpret_cast<const float4*>(&s_a[r][kk + 4]);
            float t = acc[r];
            t = fmaf(a0.x, w[0], t); t = fmaf(a0.y, w[1], t);
            t = fmaf(a0.z, w[2], t); t = fmaf(a0.w, w[3], t);
            t = fmaf(a1.x, w[4], t); t = fmaf(a1.y, w[5], t);
            t = fmaf(a1.z, w[6], t); t = fmaf(a1.w, w[7], t);
            acc[r] = t;
        }
    }

    float* yp = (WHICH ? g_y_part : g_up_part)
              + (size_t)blockIdx.y * 64 * NCOLS + c;
#pragma unroll
    for (int r = 0; r < 64; r++) yp[r * NCOLS] = acc[r];
}

// ---------------------------------------------------------------------------
// Per-batch: conv, silu, block-diag q/k/v, gate logits, gates, n_new, den.
// One block per batch, 256 threads.
// ---------------------------------------------------------------------------
__global__ __launch_bounds__(256) void k_small(
    const float* __restrict__ conv_state, const float* __restrict__ conv_w,
    const float* __restrict__ conv_b,     const float* __restrict__ Wq,
    const float* __restrict__ Wk,         const float* __restrict__ Wv,
    const float* __restrict__ Wi,         const float* __restrict__ bi,
    const float* __restrict__ Wf,         const float* __restrict__ bf,
    const float* __restrict__ n_in,       const float* __restrict__ m_in,
    float* __restrict__ out)
{
    __shared__ float s_cva[HID], s_x[HID], s_q[HID], s_k[HID], s_v[HID];
    __shared__ float s_part[8][8];
    __shared__ float s_logit[8];
    __shared__ float s_gate[4][4];   // [h]: ip, fp, exp(-m_new)

    const int b = blockIdx.x, t = threadIdx.x;
    const int lane = t & 31, wrp = t >> 5;

    // Stage 1: up partial-sum, conv, silu(z)
    for (int hh = t; hh < HID; hh += 256) {
        float xv = 0.f, zv = 0.f;
#pragma unroll
        for (int p = 0; p < 8; p++) {
            xv += g_up_part[p * 262144 + b * 4096 + hh];
            zv += g_up_part[p * 262144 + b * 4096 + 2048 + hh];
        }
        float cs0 = conv_state[b * KSZ * HID + 1 * HID + hh];
        float cs1 = conv_state[b * KSZ * HID + 2 * HID + hh];
        float cs2 = conv_state[b * KSZ * HID + 3 * HID + hh];
        float cs3 = xv;
        float* ocs = out + OFF_CS + b * KSZ * HID;
        ocs[0 * HID + hh] = cs0; ocs[1 * HID + hh] = cs1;
        ocs[2 * HID + hh] = cs2; ocs[3 * HID + hh] = cs3;

        float cx = cs0 * conv_w[hh] + cs1 * conv_w[HID + hh]
                 + cs2 * conv_w[2 * HID + hh] + cs3 * conv_w[3 * HID + hh]
                 + conv_b[hh];
        float cva = cx / (1.f + expf(-cx));
        s_cva[hh] = cva;
        s_x[hh]   = xv;
        g_cva[b * HID + hh] = cva;
        g_sz [b * HID + hh] = zv / (1.f + expf(-zv));
    }
    __syncthreads();

    // Stage 2: block-diagonal 4x4 projections
    for (int nb = t; nb < NB; nb += 256) {
        float a0 = s_cva[nb*4+0], a1 = s_cva[nb*4+1],
              a2 = s_cva[nb*4+2], a3 = s_cva[nb*4+3];
        float x0 = s_x[nb*4+0], x1 = s_x[nb*4+1],
              x2 = s_x[nb*4+2], x3 = s_x[nb*4+3];
        const float* wq = Wq + nb * 16;
        const float* wk = Wk + nb * 16;
        const float* wv = Wv + nb * 16;
#pragma unroll
        for (int e = 0; e < 4; e++) {
            float qv = a0*wq[e] + a1*wq[4+e] + a2*wq[8+e] + a3*wq[12+e];
            float kv = a0*wk[e] + a1*wk[4+e] + a2*wk[8+e] + a3*wk[12+e];
            float vv = x0*wv[e] + x1*wv[4+e] + x2*wv[8+e] + x3*wv[12+e];
            s_q[nb*4+e] = qv; s_k[nb*4+e] = kv; s_v[nb*4+e] = vv;
            g_q[b * HID + nb*4 + e] = qv;
            g_v[b * HID + nb*4 + e] = vv;
        }
    }
    __syncthreads();

    // Stage 3: gate logits  (qkv = [q,k,v] @ Wi/Wf)
    float accI[4] = {0,0,0,0}, accF[4] = {0,0,0,0};
    for (int j = t; j < HID; j += 256) {
        float qv = s_q[j], kv = s_k[j], vv = s_v[j];
#pragma unroll
        for (int h = 0; h < 4; h++) {
            accI[h] += qv * Wi[j*4+h] + kv * Wi[(HID+j)*4+h] + vv * Wi[(2*HID+j)*4+h];
            accF[h] += qv * Wf[j*4+h] + kv * Wf[(HID+j)*4+h] + vv * Wf[(2*HID+j)*4+h];
        }
    }
#pragma unroll
    for (int v8 = 0; v8 < 8; v8++) {
        float x = (v8 < 4) ? accI[v8] : accF[v8 - 4];
#pragma unroll
        for (int o = 16; o; o >>= 1) x += __shfl_down_sync(0xffffffffu, x, o);
        if (lane == 0) s_part[v8][wrp] = x;
    }
    __syncthreads();
    if (t < 8) {
        float s = 0.f;
#pragma unroll
        for (int w2 = 0; w2 < 8; w2++) s += s_part[t][w2];
        s_logit[t] = s;
    }
    __syncthreads();

    if (t < 4) {
        float it = s_logit[t]     + bi[t];
        float ft = s_logit[4 + t] + bf[t];
        // log_f = -softplus(-ft), numerically stable
        float lf = (ft >= 0.f) ? -log1pf(expf(-ft)) : (ft - log1pf(expf(ft)));
        float mo = m_in[b * 4 + t];
        float mn = fmaxf(lf + mo, it);
        float ip = expf(it - mn);
        float fp = expf(lf + mo - mn);
        out[OFF_M + b * 4 + t] = mn;
        s_gate[t][0] = ip; s_gate[t][1] = fp; s_gate[t][2] = expf(-mn);
        g_fp[b * 4 + t] = fp;
    }
    __syncthreads();

    // Stage 4: n_new, i_p*k_scaled, den
    float qn[4] = {0,0,0,0};
#pragma unroll
    for (int h = 0; h < 4; h++) {
        float ip = s_gate[h][0], fp = s_gate[h][1];
        for (int dd = t; dd < HD; dd += 256) {
            int d = h * HD + dd;
            float ik = ip * s_k[d] * RSQRT_HD;
            float nn = fp * n_in[b * HID + d] + ik;
            out[OFF_N + b * HID + d] = nn;
            g_ik[b * HID + d] = ik;
            qn[h] += s_q[d] * nn;
        }
    }
#pragma unroll
    for (int h = 0; h < 4; h++) {
        float x = qn[h];
#pragma unroll
        for (int o = 16; o; o >>= 1) x += __shfl_down_sync(0xffffffffu, x, o);
        if (lane == 0) s_part[h][wrp] = x;
    }
    __syncthreads();
    if (t < 4) {
        float s = 0.f;
#pragma unroll
        for (int w2 = 0; w2 < 8; w2++) s += s_part[t][w2];
        g_den[b * 4 + t] = fmaxf(fabsf(s), s_gate[t][2]) + EPSF;
    }
}

// ---------------------------------------------------------------------------
// Big fused kernel: C_new stream + nom = q^T C_new + layernorm + epilogue.
// One block per (b,h); thread = column e.
// ---------------------------------------------------------------------------
__device__ __forceinline__ float block_sum_512(float v, float* s_red)
{
    int t = threadIdx.x, lane = t & 31, wrp = t >> 5;
#pragma unroll
    for (int o = 16; o; o >>= 1) v += __shfl_down_sync(0xffffffffu, v, o);
    if (lane == 0) s_red[wrp] = v;
    __syncthreads();
    if (wrp == 0) {
        float x = (lane < 16) ? s_red[lane] : 0.f;
#pragma unroll
        for (int o = 8; o; o >>= 1) x += __shfl_down_sync(0xffffffffu, x, o);
        if (lane == 0) s_red[16] = x;
    }
    __syncthreads();
    float r = s_red[16];
    __syncthreads();
    return r;
}

__global__ __launch_bounds__(512) void k_big(const float* __restrict__ C,
                                             const float* __restrict__ norm_scale,
                                             const float* __restrict__ skipv,
                                             float* __restrict__ out)
{
    __shared__ float s_q[HD], s_ik[HD];
    __shared__ float s_red[17];
    const int bh = blockIdx.x;
    const int b = bh >> 2, h = bh & 3;
    const int e = threadIdx.x;

    s_q[e]  = g_q [b * HID + h * HD + e];
    s_ik[e] = g_ik[b * HID + h * HD + e];
    __syncthreads();

    const float vv = g_v[b * HID + h * HD + e];
    const float fp = g_fp[bh];
    const float* Cin  = C   + (size_t)bh * HD * HD + e;
    float*       Cout = out + OFF_C + (size_t)bh * HD * HD + e;

    float nom0 = 0.f, nom1 = 0.f, nom2 = 0.f, nom3 = 0.f;
    const float4* q4  = reinterpret_cast<const float4*>(s_q);
    const float4* ik4 = reinterpret_cast<const float4*>(s_ik);

#pragma unroll 2
    for (int d4 = 0; d4 < 128; d4++) {
        float4 qd = q4[d4], ikd = ik4[d4];
        const float* ci = Cin  + d4 * 4 * HD;
        float*       co = Cout + d4 * 4 * HD;
        float c0 = fmaf(fp, ci[0],      ikd.x * vv);
        float c1 = fmaf(fp, ci[HD],     ikd.y * vv);
        float c2 = fmaf(fp, ci[2*HD],   ikd.z * vv);
        float c3 = fmaf(fp, ci[3*HD],   ikd.w * vv);
        co[0] = c0; co[HD] = c1; co[2*HD] = c2; co[3*HD] = c3;
        nom0 = fmaf(qd.x, c0, nom0); nom1 = fmaf(qd.y, c1, nom1);
        nom2 = fmaf(qd.z, c2, nom2); nom3 = fmaf(qd.w, c3, nom3);
    }
    float nom = (nom0 + nom1) + (nom2 + nom3);
    float ht  = nom / g_den[bh];

    // Layernorm over e (two-pass for numerical safety)
    float mu  = block_sum_512(ht, s_red) * (1.f / 512.f);
    float df  = ht - mu;
    float var = block_sum_512(df * df, s_red) * (1.f / 512.f);
    float hn  = df * rsqrtf(var + EPSF) * norm_scale[h * HD + e];

    int ch = h * HD + e;
    float hv = hn + skipv[ch] * g_cva[b * HID + ch];
    hv *= g_sz[b * HID + ch];
    g_h[b * HID + ch] = hv;
}

// ---------------------------------------------------------------------------
// y = sum of down-proj k-split partials
// ---------------------------------------------------------------------------
__global__ void k_reduce_y(float* __restrict__ out)
{
    int i = blockIdx.x * 256 + threadIdx.x;
    float s = 0.f;
#pragma unroll
    for (int p = 0; p < 16; p++) s += g_y_part[p * 65536 + i];
    out[OFF_Y + i] = s;
}

// ---------------------------------------------------------------------------
extern "C" void kernel_launch(void* const* d_in, const int* in_sizes, int n_in,
                              void* d_out, int out_size)
{
    const float* inputs     = (const float*)d_in[0];
    const float* C          = (const float*)d_in[1];
    const float* n_in_p     = (const float*)d_in[2];
    const float* m_in_p     = (const float*)d_in[3];
    const float* conv_state = (const float*)d_in[4];
    const float* W_up       = (const float*)d_in[5];
    const float* conv_w     = (const float*)d_in[6];
    const float* conv_b     = (const float*)d_in[7];
    const float* Wq         = (const float*)d_in[8];
    const float* Wk         = (const float*)d_in[9];
    const float* Wv         = (const float*)d_in[10];
    const float* Wi         = (const float*)d_in[11];
    const float* bi         = (const float*)d_in[12];
    const float* Wf         = (const float*)d_in[13];
    const float* bf         = (const float*)d_in[14];
    const float* norm_scale = (const float*)d_in[15];
    const float* skipv      = (const float*)d_in[16];
    const float* W_down     = (const float*)d_in[17];
    float* out = (float*)d_out;

    // 1) up = inputs @ W_up  (K=1024, split 8)
    k_gemm64<4096, 128, 1024, 0><<<dim3(32, 8), 128>>>(inputs, W_up);
    // 2) per-batch gates/conv/qkv/n_new/den
    k_small<<<64, 256>>>(conv_state, conv_w, conv_b, Wq, Wk, Wv,
                         Wi, bi, Wf, bf, n_in_p, m_in_p, out);
    // 3) fused C_new + nom + layernorm + epilogue
    k_big<<<256, 512>>>(C, norm_scale, skipv, out);
    // 4) y partials = h @ W_down (K=2048, split 16; A = g_h resolved in-device)
    k_gemm64<1024, 128, 2048, 1><<<dim3(8, 16), 128>>>(nullptr, W_down);
    // 5) y reduction
    k_reduce_y<<<256, 256>>>(out);
}

// round 3
// speedup vs baseline: 1.2315x; 1.2315x over previous
#include <cuda_runtime.h>
#include <math.h>

// Problem constants
#define BB   64
#define FF   1024
#define HID  2048
#define NHD  4
#define KSZ  4
#define HD   512
#define NB   512
#define EPSF 1e-6f
#define RSQRT_HD 0.044194173824159216f   // 1/sqrt(512)

// Output layout: concat(y, C_new, n_new, m_new, conv_state_new), fp32
#define OFF_Y  0
#define OFF_C  65536
#define OFF_N  67174400
#define OFF_M  67305472
#define OFF_CS 67305728

#define UP_SPLITS 16
#define DN_SPLITS 32

// Scratch (static device memory; no allocations anywhere)
__device__ float g_up_part[UP_SPLITS * 64 * 4096];  // up-GEMM k-split partials
__device__ float g_y_part [DN_SPLITS * 64 * 1024];  // down-GEMM k-split partials
__device__ float g_q  [BB * HID];
__device__ float g_v  [BB * HID];
__device__ float g_ik [BB * HID];            // i_p * k / sqrt(HD)
__device__ float g_cva[BB * HID];            // silu(conv_x)
__device__ float g_sz [BB * HID];            // silu(z)
__device__ float g_h  [BB * HID];            // pre-down-proj hidden
__device__ float g_fp [BB * NHD];
__device__ float g_den[BB * NHD];            // max(|q^T n_new|, exp(-m_new)) + eps

// ---------------------------------------------------------------------------
// GEMM: Y[64, NCOLS] = A[64, LDIN] @ W[K, NCOLS], k-split partials.
// Re-tiled for occupancy: thread owns 1 column x 32 rows (32 accumulators,
// ~48 regs). grid = (NCOLS/128, K/KCHUNK, 64/32).
// WHICH=0: A = external (inputs) -> g_up_part
// WHICH=1: A = g_h (device symbol) -> g_y_part
// ---------------------------------------------------------------------------
template<int NCOLS, int KCHUNK, int LDIN, int WHICH>
__global__ __launch_bounds__(128) void k_gemm64(const float* __restrict__ Aext,
                                                const float* __restrict__ W)
{
    __shared__ float s_a[32][KCHUNK];
    const int c  = blockIdx.x * 128 + threadIdx.x;
    const int k0 = blockIdx.y * KCHUNK;
    const int r0 = blockIdx.z * 32;

    const float* A = WHICH ? (const float*)g_h : Aext;

    // load A tile [r0..r0+31, k0..k0+KCHUNK) into shared (float4 coalesced)
    {
        const int nv = 32 * (KCHUNK / 4);
        float4* s4 = reinterpret_cast<float4*>(&s_a[0][0]);
        for (int i = threadIdx.x; i < nv; i += 128) {
            int r = i / (KCHUNK / 4), kk4 = i % (KCHUNK / 4);
            s4[i] = *reinterpret_cast<const float4*>(
                        &A[(r0 + r) * LDIN + k0 + kk4 * 4]);
        }
    }
    __syncthreads();

    float acc[32];
#pragma unroll
    for (int r = 0; r < 32; r++) acc[r] = 0.f;

#pragma unroll 2
    for (int kk = 0; kk < KCHUNK; kk += 4) {
        float w0 = W[(size_t)(k0 + kk + 0) * NCOLS + c];
        float w1 = W[(size_t)(k0 + kk + 1) * NCOLS + c];
        float w2 = W[(size_t)(k0 + kk + 2) * NCOLS + c];
        float w3 = W[(size_t)(k0 + kk + 3) * NCOLS + c];
#pragma unroll
        for (int r = 0; r < 32; r++) {
            float4 a = *reinterpret_cast<const float4*>(&s_a[r][kk]);
            float t = acc[r];
            t = fmaf(a.x, w0, t); t = fmaf(a.y, w1, t);
            t = fmaf(a.z, w2, t); t = fmaf(a.w, w3, t);
            acc[r] = t;
        }
    }

    float* yp = (WHICH ? g_y_part : g_up_part)
              + (size_t)blockIdx.y * 64 * NCOLS + (size_t)r0 * NCOLS + c;
#pragma unroll
    for (int r = 0; r < 32; r++) yp[r * NCOLS] = acc[r];
}

// ---------------------------------------------------------------------------
// Per-batch: conv, silu, block-diag q/k/v, gate logits, gates, n_new, den.
// One block per batch, 256 threads.
// ---------------------------------------------------------------------------
__global__ __launch_bounds__(256) void k_small(
    const float* __restrict__ conv_state, const float* __restrict__ conv_w,
    const float* __restrict__ conv_b,     const float* __restrict__ Wq,
    const float* __restrict__ Wk,         const float* __restrict__ Wv,
    const float* __restrict__ Wi,         const float* __restrict__ bi,
    const float* __restrict__ Wf,         const float* __restrict__ bf,
    const float* __restrict__ n_in,       const float* __restrict__ m_in,
    float* __restrict__ out)
{
    __shared__ float s_cva[HID], s_x[HID], s_q[HID], s_k[HID], s_v[HID];
    __shared__ float s_part[8][8];
    __shared__ float s_logit[8];
    __shared__ float s_gate[4][4];   // [h]: ip, fp, exp(-m_new)

    const int b = blockIdx.x, t = threadIdx.x;
    const int lane = t & 31, wrp = t >> 5;

    // Stage 1: up partial-sum, conv, silu(z)
    for (int hh = t; hh < HID; hh += 256) {
        float xv = 0.f, zv = 0.f;
#pragma unroll
        for (int p = 0; p < UP_SPLITS; p++) {
            xv += g_up_part[p * 262144 + b * 4096 + hh];
            zv += g_up_part[p * 262144 + b * 4096 + 2048 + hh];
        }
        float cs0 = conv_state[b * KSZ * HID + 1 * HID + hh];
        float cs1 = conv_state[b * KSZ * HID + 2 * HID + hh];
        float cs2 = conv_state[b * KSZ * HID + 3 * HID + hh];
        float cs3 = xv;
        float* ocs = out + OFF_CS + b * KSZ * HID;
        ocs[0 * HID + hh] = cs0; ocs[1 * HID + hh] = cs1;
        ocs[2 * HID + hh] = cs2; ocs[3 * HID + hh] = cs3;

        float cx = cs0 * conv_w[hh] + cs1 * conv_w[HID + hh]
                 + cs2 * conv_w[2 * HID + hh] + cs3 * conv_w[3 * HID + hh]
                 + conv_b[hh];
        float cva = cx / (1.f + expf(-cx));
        s_cva[hh] = cva;
        s_x[hh]   = xv;
        g_cva[b * HID + hh] = cva;
        g_sz [b * HID + hh] = zv / (1.f + expf(-zv));
    }
    __syncthreads();

    // Stage 2: block-diagonal 4x4 projections
    for (int nb = t; nb < NB; nb += 256) {
        float a0 = s_cva[nb*4+0], a1 = s_cva[nb*4+1],
              a2 = s_cva[nb*4+2], a3 = s_cva[nb*4+3];
        float x0 = s_x[nb*4+0], x1 = s_x[nb*4+1],
              x2 = s_x[nb*4+2], x3 = s_x[nb*4+3];
        const float* wq = Wq + nb * 16;
        const float* wk = Wk + nb * 16;
        const float* wv = Wv + nb * 16;
#pragma unroll
        for (int e = 0; e < 4; e++) {
            float qv = a0*wq[e] + a1*wq[4+e] + a2*wq[8+e] + a3*wq[12+e];
            float kv = a0*wk[e] + a1*wk[4+e] + a2*wk[8+e] + a3*wk[12+e];
            float vv = x0*wv[e] + x1*wv[4+e] + x2*wv[8+e] + x3*wv[12+e];
            s_q[nb*4+e] = qv; s_k[nb*4+e] = kv; s_v[nb*4+e] = vv;
            g_q[b * HID + nb*4 + e] = qv;
            g_v[b * HID + nb*4 + e] = vv;
        }
    }
    __syncthreads();

    // Stage 3: gate logits  (qkv = [q,k,v] @ Wi/Wf)
    float accI[4] = {0,0,0,0}, accF[4] = {0,0,0,0};
    for (int j = t; j < HID; j += 256) {
        float qv = s_q[j], kv = s_k[j], vv = s_v[j];
#pragma unroll
        for (int h = 0; h < 4; h++) {
            accI[h] += qv * Wi[j*4+h] + kv * Wi[(HID+j)*4+h] + vv * Wi[(2*HID+j)*4+h];
            accF[h] += qv * Wf[j*4+h] + kv * Wf[(HID+j)*4+h] + vv * Wf[(2*HID+j)*4+h];
        }
    }
#pragma unroll
    for (int v8 = 0; v8 < 8; v8++) {
        float x = (v8 < 4) ? accI[v8] : accF[v8 - 4];
#pragma unroll
        for (int o = 16; o; o >>= 1) x += __shfl_down_sync(0xffffffffu, x, o);
        if (lane == 0) s_part[v8][wrp] = x;
    }
    __syncthreads();
    if (t < 8) {
        float s = 0.f;
#pragma unroll
        for (int w2 = 0; w2 < 8; w2++) s += s_part[t][w2];
        s_logit[t] = s;
    }
    __syncthreads();

    if (t < 4) {
        float it = s_logit[t]     + bi[t];
        float ft = s_logit[4 + t] + bf[t];
        // log_f = -softplus(-ft), numerically stable
        float lf = (ft >= 0.f) ? -log1pf(expf(-ft)) : (ft - log1pf(expf(ft)));
        float mo = m_in[b * 4 + t];
        float mn = fmaxf(lf + mo, it);
        float ip = expf(it - mn);
        float fp = expf(lf + mo - mn);
        out[OFF_M + b * 4 + t] = mn;
        s_gate[t][0] = ip; s_gate[t][1] = fp; s_gate[t][2] = expf(-mn);
        g_fp[b * 4 + t] = fp;
    }
    __syncthreads();

    // Stage 4: n_new, i_p*k_scaled, den
    float qn[4] = {0,0,0,0};
#pragma unroll
    for (int h = 0; h < 4; h++) {
        float ip = s_gate[h][0], fp = s_gate[h][1];
        for (int dd = t; dd < HD; dd += 256) {
            int d = h * HD + dd;
            float ik = ip * s_k[d] * RSQRT_HD;
            float nn = fp * n_in[b * HID + d] + ik;
            out[OFF_N + b * HID + d] = nn;
            g_ik[b * HID + d] = ik;
            qn[h] += s_q[d] * nn;
        }
    }
#pragma unroll
    for (int h = 0; h < 4; h++) {
        float x = qn[h];
#pragma unroll
        for (int o = 16; o; o >>= 1) x += __shfl_down_sync(0xffffffffu, x, o);
        if (lane == 0) s_part[h][wrp] = x;
    }
    __syncthreads();
    if (t < 4) {
        float s = 0.f;
#pragma unroll
        for (int w2 = 0; w2 < 8; w2++) s += s_part[t][w2];
        g_den[b * 4 + t] = fmaxf(fabsf(s), s_gate[t][2]) + EPSF;
    }
}

// ---------------------------------------------------------------------------
// Big fused kernel: C_new stream + nom = q^T C_new + layernorm + epilogue.
// One block per (b,h); thread = column e.
// ---------------------------------------------------------------------------
__device__ __forceinline__ float block_sum_512(float v, float* s_red)
{
    int t = threadIdx.x, lane = t & 31, wrp = t >> 5;
#pragma unroll
    for (int o = 16; o; o >>= 1) v += __shfl_down_sync(0xffffffffu, v, o);
    if (lane == 0) s_red[wrp] = v;
    __syncthreads();
    if (wrp == 0) {
        float x = (lane < 16) ? s_red[lane] : 0.f;
#pragma unroll
        for (int o = 8; o; o >>= 1) x += __shfl_down_sync(0xffffffffu, x, o);
        if (lane == 0) s_red[16] = x;
    }
    __syncthreads();
    float r = s_red[16];
    __syncthreads();
    return r;
}

__global__ __launch_bounds__(512) void k_big(const float* __restrict__ C,
                                             const float* __restrict__ norm_scale,
                                             const float* __restrict__ skipv,
                                             float* __restrict__ out)
{
    __shared__ float s_q[HD], s_ik[HD];
    __shared__ float s_red[17];
    const int bh = blockIdx.x;
    const int b = bh >> 2, h = bh & 3;
    const int e = threadIdx.x;

    s_q[e]  = g_q [b * HID + h * HD + e];
    s_ik[e] = g_ik[b * HID + h * HD + e];
    __syncthreads();

    const float vv = g_v[b * HID + h * HD + e];
    const float fp = g_fp[bh];
    const float* Cin  = C   + (size_t)bh * HD * HD + e;
    float*       Cout = out + OFF_C + (size_t)bh * HD * HD + e;

    float nom0 = 0.f, nom1 = 0.f, nom2 = 0.f, nom3 = 0.f;
    const float4* q4  = reinterpret_cast<const float4*>(s_q);
    const float4* ik4 = reinterpret_cast<const float4*>(s_ik);

#pragma unroll 4
    for (int d4 = 0; d4 < 128; d4++) {
        float4 qd = q4[d4], ikd = ik4[d4];
        const float* ci = Cin  + d4 * 4 * HD;
        float*       co = Cout + d4 * 4 * HD;
        float c0 = fmaf(fp, ci[0],      ikd.x * vv);
        float c1 = fmaf(fp, ci[HD],     ikd.y * vv);
        float c2 = fmaf(fp, ci[2*HD],   ikd.z * vv);
        float c3 = fmaf(fp, ci[3*HD],   ikd.w * vv);
        co[0] = c0; co[HD] = c1; co[2*HD] = c2; co[3*HD] = c3;
        nom0 = fmaf(qd.x, c0, nom0); nom1 = fmaf(qd.y, c1, nom1);
        nom2 = fmaf(qd.z, c2, nom2); nom3 = fmaf(qd.w, c3, nom3);
    }
    float nom = (nom0 + nom1) + (nom2 + nom3);
    float ht  = nom / g_den[bh];

    // Layernorm over e (two-pass)
    float mu  = block_sum_512(ht, s_red) * (1.f / 512.f);
    float df  = ht - mu;
    float var = block_sum_512(df * df, s_red) * (1.f / 512.f);
    float hn  = df * rsqrtf(var + EPSF) * norm_scale[h * HD + e];

    int ch = h * HD + e;
    float hv = hn + skipv[ch] * g_cva[b * HID + ch];
    hv *= g_sz[b * HID + ch];
    g_h[b * HID + ch] = hv;
}

// ---------------------------------------------------------------------------
// y = sum of down-proj k-split partials
// ---------------------------------------------------------------------------
__global__ void k_reduce_y(float* __restrict__ out)
{
    int i = blockIdx.x * 256 + threadIdx.x;
    float s = 0.f;
#pragma unroll
    for (int p = 0; p < DN_SPLITS; p++) s += g_y_part[p * 65536 + i];
    out[OFF_Y + i] = s;
}

// ---------------------------------------------------------------------------
extern "C" void kernel_launch(void* const* d_in, const int* in_sizes, int n_in,
                              void* d_out, int out_size)
{
    const float* inputs     = (const float*)d_in[0];
    const float* C          = (const float*)d_in[1];
    const float* n_in_p     = (const float*)d_in[2];
    const float* m_in_p     = (const float*)d_in[3];
    const float* conv_state = (const float*)d_in[4];
    const float* W_up       = (const float*)d_in[5];
    const float* conv_w     = (const float*)d_in[6];
    const float* conv_b     = (const float*)d_in[7];
    const float* Wq         = (const float*)d_in[8];
    const float* Wk         = (const float*)d_in[9];
    const float* Wv         = (const float*)d_in[10];
    const float* Wi         = (const float*)d_in[11];
    const float* bi         = (const float*)d_in[12];
    const float* Wf         = (const float*)d_in[13];
    const float* bf         = (const float*)d_in[14];
    const float* norm_scale = (const float*)d_in[15];
    const float* skipv      = (const float*)d_in[16];
    const float* W_down     = (const float*)d_in[17];
    float* out = (float*)d_out;

    // 1) up = inputs @ W_up  (K=1024, 16 splits x 2 row groups, 1024 blocks)
    k_gemm64<4096, 64, 1024, 0><<<dim3(32, UP_SPLITS, 2), 128>>>(inputs, W_up);
    // 2) per-batch gates/conv/qkv/n_new/den
    k_small<<<64, 256>>>(conv_state, conv_w, conv_b, Wq, Wk, Wv,
                         Wi, bi, Wf, bf, n_in_p, m_in_p, out);
    // 3) fused C_new + nom + layernorm + epilogue
    k_big<<<256, 512>>>(C, norm_scale, skipv, out);
    // 4) y partials = h @ W_down (K=2048, 32 splits x 2 row groups, 512 blocks)
    k_gemm64<1024, 64, 2048, 1><<<dim3(8, DN_SPLITS, 2), 128>>>(nullptr, W_down);
    // 5) y reduction
    k_reduce_y<<<256, 256>>>(out);
}